// round 4
// baseline (speedup 1.0000x reference)
#include <cuda_runtime.h>
#include <cstdint>

typedef unsigned long long u64;

#define TILE_B 32
#define THREADS 512
#define APAD 36
#define LOG_SQRT_2PI 0.9189385332046727f

__device__ __forceinline__ u64 bcast2(float x) {
    u64 r;
    asm("mov.b64 %0, {%1,%2};" : "=l"(r) : "f"(x), "f"(x));
    return r;
}
__device__ __forceinline__ void ffma2(u64& d, u64 a, u64 b) {
    asm("fma.rn.f32x2 %0, %1, %2, %0;" : "+l"(d) : "l"(a), "l"(b));
}
__device__ __forceinline__ float2 unpack2(u64 v) {
    float2 f;
    asm("mov.b64 {%0,%1}, %2;" : "=f"(f.x), "=f"(f.y) : "l"(v));
    return f;
}
__device__ __forceinline__ float lrelu(float v) { return v > 0.f ? v : 0.01f * v; }

// Transposed-activation GEMM: sAT[k][r] (stride APAD) -> sCT[n][r] (stride APAD).
// Each thread owns 1 column, TILE_B/RG rows, row-paired f32x2 accumulators.
template <int K, int N, bool RELU>
__device__ __forceinline__ void gemm_T(
    const float* __restrict__ W, const float* __restrict__ bias,
    const float* __restrict__ sAT, float* __restrict__ sCT)
{
    constexpr int RG  = THREADS / N;    // 1, 2, 4
    constexpr int RPT = TILE_B / RG;    // 32, 16, 8
    const int t   = threadIdx.x;
    const int col = t % N;
    const int row0 = (t / N) * RPT;

    u64 acc[RPT / 2];
#pragma unroll
    for (int i = 0; i < RPT / 2; i++) acc[i] = 0ull;

    const float* Wc = W + col;
    const float* aBase = sAT + row0;

    float wc[4], wn[4];
#pragma unroll
    for (int u = 0; u < 4; u++) wc[u] = Wc[u * N];

#pragma unroll 2
    for (int k = 0; k < K; k += 4) {
        if (k + 4 < K) {
#pragma unroll
            for (int u = 0; u < 4; u++) wn[u] = Wc[(size_t)(k + 4 + u) * N];
        }
#pragma unroll
        for (int u = 0; u < 4; u++) {
            const u64 b = bcast2(wc[u]);
            const ulonglong2* ap =
                reinterpret_cast<const ulonglong2*>(aBase + (k + u) * APAD);
#pragma unroll
            for (int j = 0; j < RPT / 4; j++) {
                ulonglong2 av = ap[j];
                ffma2(acc[2 * j],     av.x, b);
                ffma2(acc[2 * j + 1], av.y, b);
            }
        }
#pragma unroll
        for (int u = 0; u < 4; u++) wc[u] = wn[u];
    }

    const float bc = bias[col];
    float* dst = sCT + col * APAD + row0;
#pragma unroll
    for (int j = 0; j < RPT / 4; j++) {
        float2 v0 = unpack2(acc[2 * j]);
        float2 v1 = unpack2(acc[2 * j + 1]);
        float c0 = v0.x + bc, c1 = v0.y + bc, c2 = v1.x + bc, c3 = v1.y + bc;
        if (RELU) { c0 = lrelu(c0); c1 = lrelu(c1); c2 = lrelu(c2); c3 = lrelu(c3); }
        *reinterpret_cast<float4*>(dst + 4 * j) = make_float4(c0, c1, c2, c3);
    }
}

// Shared memory layout (floats)
#define OFF_INT    0                    // 256*36 = 9216  (obs_stat^T)
#define OFF_GOALT  9216                 // 128*36 = 4608  (obs_goal^T)
#define OFF_AT     13824                // 512*36 = 18432
#define OFF_BT     32256                // 256*36 = 9216
#define OFF_CT     41472                // 256*36 = 9216  (sg^T / h^T)
#define OFF_WGDUP  50688                // 8*520 = 4160   (Wgate dup'd {w,w})
#define OFF_GATE   54848                // 256
#define OFF_SUM1   55104                // 640
#define OFF_SUM2   55744                // 640
#define OFF_ACT    56384                // 640
#define SMEM_FLOATS 57024
#define SMEM_BYTES (SMEM_FLOATS * 4)    // 228096 B
// p-loop reuse of [INT|GOALT|AT] region (free after W2):
#define OFF_WP2DUP 0                    // 40*520 = 20800 (Wp2[p] dup'd {w,w})
#define OFF_PS     20800                // 32*40 = 1280
#define OFF_BP2    22080                // 40

__global__ __launch_bounds__(THREADS, 1) void actor_kernel(
    const float* __restrict__ obs, const float* __restrict__ actions,
    const float* __restrict__ W1, const float* __restrict__ b1,
    const float* __restrict__ W2, const float* __restrict__ b2,
    const float* __restrict__ Wp1, const float* __restrict__ bp1,
    const float* __restrict__ Wp2, const float* __restrict__ bp2,
    const float* __restrict__ Ws1, const float* __restrict__ bs1,
    const float* __restrict__ Ws2, const float* __restrict__ bs2,
    const float* __restrict__ Ws3, const float* __restrict__ bs3,
    const float* __restrict__ Wg1, const float* __restrict__ bg1,
    const float* __restrict__ Wg2, const float* __restrict__ bg2,
    const float* __restrict__ Wg3, const float* __restrict__ bg3,
    const float* __restrict__ Wgate, const float* __restrict__ bgate,
    float* __restrict__ out)
{
    extern __shared__ float sm[];
    float* sInT  = sm + OFF_INT;
    float* sGoalT= sm + OFF_GOALT;
    float* sAT   = sm + OFF_AT;
    float* sBT   = sm + OFF_BT;
    float* sCT   = sm + OFF_CT;
    float* sWgD  = sm + OFF_WGDUP;
    float* sGate = sm + OFF_GATE;
    float* sSum1 = sm + OFF_SUM1;
    float* sSum2 = sm + OFF_SUM2;
    float* sAct  = sm + OFF_ACT;
    float* sWp2D = sm + OFF_WP2DUP;
    float* sPS   = sm + OFF_PS;
    float* sBp2  = sm + OFF_BP2;

    const int t = threadIdx.x;
    const int rowBase = blockIdx.x * TILE_B;

    // ---- load inputs (transposed), stage dup'd Wgate, init sums ----
    {
        // i -> (b = i%32, c4 = i/32): lanes span b -> conflict-free STS
        for (int i = t; i < 32 * 96; i += THREADS) {
            int b = i & 31, c4 = i >> 5;
            float4 v = *reinterpret_cast<const float4*>(
                obs + (size_t)(rowBase + b) * 384 + c4 * 4);
            int k = c4 * 4;
            if (k < 256) {
                sInT[(k + 0) * APAD + b] = v.x;
                sInT[(k + 1) * APAD + b] = v.y;
                sInT[(k + 2) * APAD + b] = v.z;
                sInT[(k + 3) * APAD + b] = v.w;
            } else {
                int kg = k - 256;
                sGoalT[(kg + 0) * APAD + b] = v.x;
                sGoalT[(kg + 1) * APAD + b] = v.y;
                sGoalT[(kg + 2) * APAD + b] = v.z;
                sGoalT[(kg + 3) * APAD + b] = v.w;
            }
        }
        for (int i = t; i < 640; i += THREADS) sAct[i] = actions[(size_t)rowBase * 20 + i];
        for (int i = t; i < 2048; i += THREADS) {
            int k = i >> 3, p = i & 7;
            *reinterpret_cast<u64*>(sWgD + p * 520 + 2 * k) = bcast2(Wgate[i]);
        }
        for (int i = t; i < 640; i += THREADS) { sSum1[i] = 0.f; sSum2[i] = 0.f; }
    }
    __syncthreads();

    // ---- gate path (sg = lrelu applied in Ws3/Wg3 epilogue) ----
    gemm_T<256, 512, true >(Ws1, bs1, sInT,   sAT);  __syncthreads();
    gemm_T<512, 256, true >(Ws2, bs2, sAT,    sBT);  __syncthreads();
    gemm_T<256, 128, true >(Ws3, bs3, sBT,    sCT);                    // -> sg^T[0:128]
    gemm_T<128, 512, true >(Wg1, bg1, sGoalT, sAT);  __syncthreads();
    gemm_T<512, 256, true >(Wg2, bg2, sAT,    sBT);  __syncthreads();
    gemm_T<256, 128, true >(Wg3, bg3, sBT,    sCT + 128 * APAD);       // -> sg^T[128:256]
    __syncthreads();

    // ---- gate: w_gate[b][p] = exp(sg[b].Wgate[:,p] + bgate[p]) ----
    // t<128: bp = row-pair, p = primitive; row-paired f32x2, dup'd weights
    if (t < 128) {
        const int bp = t & 15, p = t >> 4;
        const float* wg = sWgD + p * 520;
        u64 acc0 = 0ull, acc1 = 0ull;
        const float* aB = sCT + 2 * bp;
#pragma unroll 4
        for (int k = 0; k < 256; k += 2) {
            ulonglong2 wp = *reinterpret_cast<const ulonglong2*>(wg + 2 * k);
            u64 a0 = *reinterpret_cast<const u64*>(aB + k * APAD);
            u64 a1 = *reinterpret_cast<const u64*>(aB + (k + 1) * APAD);
            ffma2(acc0, a0, wp.x);
            ffma2(acc1, a1, wp.y);
        }
        float2 v0 = unpack2(acc0), v1 = unpack2(acc1);
        float bg = bgate[p];
        sGate[(2 * bp) * 8 + p]     = expf(v0.x + v1.x + bg);
        sGate[(2 * bp + 1) * 8 + p] = expf(v0.y + v1.y + bg);
    }

    // ---- primitive trunk (no barrier needed before W1: disjoint regions) ----
    gemm_T<256, 512, true>(W1, b1, sInT, sAT); __syncthreads();
    gemm_T<512, 256, true>(W2, b2, sAT,  sBT); __syncthreads();
    // [INT|GOALT|AT] now free -> Wp2 dup staging + ps

    for (int p = 0; p < 8; p++) {
        // stage Wp2[p] duplicated {w,w}: [o][2k], stride 520
        const float* wp2 = Wp2 + p * (256 * 40);
        for (int i = t; i < 256 * 40; i += THREADS) {
            int k = i / 40, o = i % 40;
            *reinterpret_cast<u64*>(sWp2D + o * 520 + 2 * k) = bcast2(wp2[i]);
        }
        if (t < 40) sBp2[t] = bp2[p * 40 + t];
        // h^T = lrelu(s1 @ Wp1[p] + bp1[p])
        gemm_T<256, 256, true>(Wp1 + p * (256 * 256), bp1 + p * 256, sBT, sCT);
        __syncthreads();

        // ps: t<128: bp row-pair, og*5+q outputs; reads h^T + dup'd Wp2
        if (t < 128) {
            const int bp = t & 15, og = t >> 4;
            u64 acc5[5];
#pragma unroll
            for (int q = 0; q < 5; q++) acc5[q] = 0ull;
            const float* aB = sCT + 2 * bp;
#pragma unroll 2
            for (int k = 0; k < 256; k += 2) {
                u64 a0 = *reinterpret_cast<const u64*>(aB + k * APAD);
                u64 a1 = *reinterpret_cast<const u64*>(aB + (k + 1) * APAD);
#pragma unroll
                for (int q = 0; q < 5; q++) {
                    ulonglong2 wp = *reinterpret_cast<const ulonglong2*>(
                        sWp2D + (og * 5 + q) * 520 + 2 * k);
                    ffma2(acc5[q], a0, wp.x);
                    ffma2(acc5[q], a1, wp.y);
                }
            }
#pragma unroll
            for (int q = 0; q < 5; q++) {
                int o = og * 5 + q;
                float2 v = unpack2(acc5[q]);
                float bb = sBp2[o];
                sPS[(2 * bp) * 40 + o]     = v.x + bb;
                sPS[(2 * bp + 1) * 40 + o] = v.y + bb;
            }
        }
        __syncthreads();

        // accumulate mixture sums
        for (int i = t; i < 640; i += THREADS) {
            int b = i / 20, a = i % 20;
            float mu  = sPS[b * 40 + a];
            float sig = expf(sPS[b * 40 + 20 + a]);
            float inv = sGate[b * 8 + p] / sig;
            sSum1[i] += mu * inv;
            sSum2[i] += inv;
        }
        __syncthreads();
    }

    // ---- final log_prob / entropy ----
    if (t < 32) {
        const int b = t;
        float lp = 0.f, ent = 0.f;
#pragma unroll
        for (int a = 0; a < 20; a++) {
            float s1v = sSum1[b * 20 + a];
            float s2v = sSum2[b * 20 + a];
            float mu = s1v / s2v;
            float z = (sAct[b * 20 + a] - mu) * s2v;
            float ls = -logf(s2v);
            lp  += -0.5f * z * z - ls - LOG_SQRT_2PI;
            ent += 0.5f + LOG_SQRT_2PI + ls;
        }
        size_t row = (size_t)rowBase + b;
        out[row * 2 + 0] = lp;
        out[row * 2 + 1] = ent;
    }
}

extern "C" void kernel_launch(void* const* d_in, const int* in_sizes, int n_in,
                              void* d_out, int out_size)
{
    const float* obs    = (const float*)d_in[0];
    const float* actions= (const float*)d_in[1];
    const float* W1     = (const float*)d_in[2];
    const float* b1     = (const float*)d_in[3];
    const float* W2     = (const float*)d_in[4];
    const float* b2     = (const float*)d_in[5];
    const float* Wp1    = (const float*)d_in[6];
    const float* bp1    = (const float*)d_in[7];
    const float* Wp2    = (const float*)d_in[8];
    const float* bp2    = (const float*)d_in[9];
    const float* Ws1    = (const float*)d_in[10];
    const float* bs1    = (const float*)d_in[11];
    const float* Ws2    = (const float*)d_in[12];
    const float* bs2    = (const float*)d_in[13];
    const float* Ws3    = (const float*)d_in[14];
    const float* bs3    = (const float*)d_in[15];
    const float* Wg1    = (const float*)d_in[16];
    const float* bg1    = (const float*)d_in[17];
    const float* Wg2    = (const float*)d_in[18];
    const float* bg2    = (const float*)d_in[19];
    const float* Wg3    = (const float*)d_in[20];
    const float* bg3    = (const float*)d_in[21];
    const float* Wgate  = (const float*)d_in[22];
    const float* bgate  = (const float*)d_in[23];
    float* out = (float*)d_out;

    cudaFuncSetAttribute(actor_kernel,
                         cudaFuncAttributeMaxDynamicSharedMemorySize, SMEM_BYTES);

    const int grid = 65536 / TILE_B;  // 2048 CTAs
    actor_kernel<<<grid, THREADS, SMEM_BYTES>>>(
        obs, actions, W1, b1, W2, b2, Wp1, bp1, Wp2, bp2,
        Ws1, bs1, Ws2, bs2, Ws3, bs3, Wg1, bg1, Wg2, bg2,
        Wg3, bg3, Wgate, bgate, out);
}

// round 5
// speedup vs baseline: 1.2256x; 1.2256x over previous
#include <cuda_runtime.h>
#include <cstdint>

typedef unsigned long long u64;

#define TILE_B 32
#define THREADS 512
#define APAD 36
#define LOG_SQRT_2PI 0.9189385332046727f

__device__ __forceinline__ u64 bcast2(float x) {
    u64 r;
    asm("mov.b64 %0, {%1,%2};" : "=l"(r) : "f"(x), "f"(x));
    return r;
}
__device__ __forceinline__ void ffma2(u64& d, u64 a, u64 b) {
    asm("fma.rn.f32x2 %0, %1, %2, %0;" : "+l"(d) : "l"(a), "l"(b));
}
__device__ __forceinline__ float2 unpack2(u64 v) {
    float2 f;
    asm("mov.b64 {%0,%1}, %2;" : "=f"(f.x), "=f"(f.y) : "l"(v));
    return f;
}
__device__ __forceinline__ float lrelu(float v) { return v > 0.f ? v : 0.01f * v; }

template<int CPT> struct WVec;
template<> struct WVec<4> { typedef float4 T; };
template<> struct WVec<2> { typedef float2 T; };
template<> struct WVec<1> { typedef float  T; };

__device__ __forceinline__ float getc(const float4& v, int i) {
    return i == 0 ? v.x : i == 1 ? v.y : i == 2 ? v.z : v.w;
}
__device__ __forceinline__ float getc(const float2& v, int i) { return i == 0 ? v.x : v.y; }
__device__ __forceinline__ float getc(const float&  v, int)   { return v; }

// Transposed row-paired GEMM: sAT[k][b] (stride APAD) -> sCT[n][b] (stride APAD).
// Every layer uses COLT=128 (col-groups), RG=4 row-groups, RPT=8 rows/thread.
// Thread computes CPT cols x 8 rows as 4 f32x2 row-pair accumulators per col.
// W prefetched PF k-rows ahead (>= L2 latency).
template <int K, int N, int CPT, int PF, bool RELU>
__device__ __forceinline__ void gemm_T2(
    const float* __restrict__ W, const float* __restrict__ bias,
    const float* __restrict__ sAT, float* __restrict__ sCT)
{
    constexpr int COLT = N / CPT;                     // 128 for all layers
    static_assert(COLT * 4 == THREADS, "mapping");
    typedef typename WVec<CPT>::T WT;

    const int t    = threadIdx.x;
    const int col0 = (t % COLT) * CPT;
    const int row0 = (t / COLT) * 8;                  // RPT = 8

    u64 acc[CPT][4];
#pragma unroll
    for (int c = 0; c < CPT; c++)
#pragma unroll
        for (int j = 0; j < 4; j++) acc[c][j] = 0ull;

    const float* Wc = W + col0;
    WT wbuf[PF];
#pragma unroll
    for (int i = 0; i < PF; i++)
        wbuf[i] = *reinterpret_cast<const WT*>(Wc + (size_t)i * N);

#pragma unroll 1
    for (int kb = 0; kb < K; kb += PF) {
#pragma unroll
        for (int u = 0; u < PF; u++) {
            WT wv = wbuf[u];
            if (kb + PF + u < K)
                wbuf[u] = *reinterpret_cast<const WT*>(Wc + (size_t)(kb + PF + u) * N);
            const ulonglong2* ap = reinterpret_cast<const ulonglong2*>(
                sAT + (kb + u) * APAD + row0);
            const ulonglong2 a01 = ap[0];
            const ulonglong2 a23 = ap[1];
#pragma unroll
            for (int c = 0; c < CPT; c++) {
                const u64 b = bcast2(getc(wv, c));
                ffma2(acc[c][0], a01.x, b);
                ffma2(acc[c][1], a01.y, b);
                ffma2(acc[c][2], a23.x, b);
                ffma2(acc[c][3], a23.y, b);
            }
        }
    }

#pragma unroll
    for (int c = 0; c < CPT; c++) {
        const float bc = bias[col0 + c];
        float* dst = sCT + (size_t)(col0 + c) * APAD + row0;
#pragma unroll
        for (int jj = 0; jj < 2; jj++) {
            float2 v0 = unpack2(acc[c][2 * jj]);
            float2 v1 = unpack2(acc[c][2 * jj + 1]);
            float c0 = v0.x + bc, c1 = v0.y + bc, c2 = v1.x + bc, c3 = v1.y + bc;
            if (RELU) { c0 = lrelu(c0); c1 = lrelu(c1); c2 = lrelu(c2); c3 = lrelu(c3); }
            *reinterpret_cast<float4*>(dst + 4 * jj) = make_float4(c0, c1, c2, c3);
        }
    }
}

// Shared memory layout (floats)
#define OFF_INT    0                    // 256*36 = 9216  (obs_stat^T)
#define OFF_GOALT  9216                 // 128*36 = 4608  (obs_goal^T)
#define OFF_AT     13824                // 512*36 = 18432
#define OFF_BT     32256                // 256*36 = 9216
#define OFF_CT     41472                // 256*36 = 9216  (sg^T / h^T)
#define OFF_WGDUP  50688                // 8*520 = 4160   (Wgate dup'd {w,w})
#define OFF_GATE   54848                // 256
#define OFF_SUM1   55104                // 640
#define OFF_SUM2   55744                // 640
#define OFF_ACT    56384                // 640
#define SMEM_FLOATS 57024
#define SMEM_BYTES (SMEM_FLOATS * 4)    // 228096 B
// p-loop reuse of [INT|GOALT|AT] region (free after W2):
#define OFF_WP2DUP 0                    // 40*520 = 20800 (Wp2[p] dup'd {w,w})
#define OFF_PS     20800                // 32*40 = 1280
#define OFF_BP2    22080                // 40

__global__ __launch_bounds__(THREADS, 1) void actor_kernel(
    const float* __restrict__ obs, const float* __restrict__ actions,
    const float* __restrict__ W1, const float* __restrict__ b1,
    const float* __restrict__ W2, const float* __restrict__ b2,
    const float* __restrict__ Wp1, const float* __restrict__ bp1,
    const float* __restrict__ Wp2, const float* __restrict__ bp2,
    const float* __restrict__ Ws1, const float* __restrict__ bs1,
    const float* __restrict__ Ws2, const float* __restrict__ bs2,
    const float* __restrict__ Ws3, const float* __restrict__ bs3,
    const float* __restrict__ Wg1, const float* __restrict__ bg1,
    const float* __restrict__ Wg2, const float* __restrict__ bg2,
    const float* __restrict__ Wg3, const float* __restrict__ bg3,
    const float* __restrict__ Wgate, const float* __restrict__ bgate,
    float* __restrict__ out)
{
    extern __shared__ float sm[];
    float* sInT  = sm + OFF_INT;
    float* sGoalT= sm + OFF_GOALT;
    float* sAT   = sm + OFF_AT;
    float* sBT   = sm + OFF_BT;
    float* sCT   = sm + OFF_CT;
    float* sWgD  = sm + OFF_WGDUP;
    float* sGate = sm + OFF_GATE;
    float* sSum1 = sm + OFF_SUM1;
    float* sSum2 = sm + OFF_SUM2;
    float* sAct  = sm + OFF_ACT;
    float* sWp2D = sm + OFF_WP2DUP;
    float* sPS   = sm + OFF_PS;
    float* sBp2  = sm + OFF_BP2;

    const int t = threadIdx.x;
    const int rowBase = blockIdx.x * TILE_B;

    // ---- load inputs (transposed), stage dup'd Wgate, init sums ----
    {
        for (int i = t; i < 32 * 96; i += THREADS) {
            int b = i & 31, c4 = i >> 5;
            float4 v = *reinterpret_cast<const float4*>(
                obs + (size_t)(rowBase + b) * 384 + c4 * 4);
            int k = c4 * 4;
            if (k < 256) {
                sInT[(k + 0) * APAD + b] = v.x;
                sInT[(k + 1) * APAD + b] = v.y;
                sInT[(k + 2) * APAD + b] = v.z;
                sInT[(k + 3) * APAD + b] = v.w;
            } else {
                int kg = k - 256;
                sGoalT[(kg + 0) * APAD + b] = v.x;
                sGoalT[(kg + 1) * APAD + b] = v.y;
                sGoalT[(kg + 2) * APAD + b] = v.z;
                sGoalT[(kg + 3) * APAD + b] = v.w;
            }
        }
        for (int i = t; i < 640; i += THREADS) sAct[i] = actions[(size_t)rowBase * 20 + i];
        for (int i = t; i < 2048; i += THREADS) {
            int k = i >> 3, p = i & 7;
            *reinterpret_cast<u64*>(sWgD + p * 520 + 2 * k) = bcast2(Wgate[i]);
        }
        for (int i = t; i < 640; i += THREADS) { sSum1[i] = 0.f; sSum2[i] = 0.f; }
    }
    __syncthreads();

    // ---- gate path (lrelu folded into Ws3/Wg3 epilogue) ----
    gemm_T2<256, 512, 4,  8, true>(Ws1, bs1, sInT,   sAT);  __syncthreads();
    gemm_T2<512, 256, 2, 16, true>(Ws2, bs2, sAT,    sBT);  __syncthreads();
    gemm_T2<256, 128, 1, 16, true>(Ws3, bs3, sBT,    sCT);
    gemm_T2<128, 512, 4,  8, true>(Wg1, bg1, sGoalT, sAT);  __syncthreads();
    gemm_T2<512, 256, 2, 16, true>(Wg2, bg2, sAT,    sBT);  __syncthreads();
    gemm_T2<256, 128, 1, 16, true>(Wg3, bg3, sBT,    sCT + 128 * APAD);
    __syncthreads();

    // ---- gate: w_gate[b][p] = exp(sg[b].Wgate[:,p] + bgate[p]) ----
    if (t < 128) {
        const int bp = t & 15, p = t >> 4;
        const float* wg = sWgD + p * 520;
        u64 acc0 = 0ull, acc1 = 0ull;
        const float* aB = sCT + 2 * bp;
#pragma unroll 4
        for (int k = 0; k < 256; k += 2) {
            ulonglong2 wp = *reinterpret_cast<const ulonglong2*>(wg + 2 * k);
            u64 a0 = *reinterpret_cast<const u64*>(aB + k * APAD);
            u64 a1 = *reinterpret_cast<const u64*>(aB + (k + 1) * APAD);
            ffma2(acc0, a0, wp.x);
            ffma2(acc1, a1, wp.y);
        }
        float2 v0 = unpack2(acc0), v1 = unpack2(acc1);
        float bg = bgate[p];
        sGate[(2 * bp) * 8 + p]     = expf(v0.x + v1.x + bg);
        sGate[(2 * bp + 1) * 8 + p] = expf(v0.y + v1.y + bg);
    }

    // ---- primitive trunk (disjoint smem regions vs gate stage) ----
    gemm_T2<256, 512, 4,  8, true>(W1, b1, sInT, sAT); __syncthreads();
    gemm_T2<512, 256, 2, 16, true>(W2, b2, sAT,  sBT); __syncthreads();
    // [INT|GOALT|AT] now free -> Wp2 dup staging + ps

    for (int p = 0; p < 8; p++) {
        const float* wp2 = Wp2 + p * (256 * 40);
        for (int i = t; i < 256 * 40; i += THREADS) {
            int k = i / 40, o = i % 40;
            *reinterpret_cast<u64*>(sWp2D + o * 520 + 2 * k) = bcast2(wp2[i]);
        }
        if (t < 40) sBp2[t] = bp2[p * 40 + t];
        gemm_T2<256, 256, 2, 16, true>(Wp1 + p * (256 * 256), bp1 + p * 256, sBT, sCT);
        __syncthreads();

        if (t < 128) {
            const int bp = t & 15, og = t >> 4;
            u64 acc5[5];
#pragma unroll
            for (int q = 0; q < 5; q++) acc5[q] = 0ull;
            const float* aB = sCT + 2 * bp;
#pragma unroll 2
            for (int k = 0; k < 256; k += 2) {
                u64 a0 = *reinterpret_cast<const u64*>(aB + k * APAD);
                u64 a1 = *reinterpret_cast<const u64*>(aB + (k + 1) * APAD);
#pragma unroll
                for (int q = 0; q < 5; q++) {
                    ulonglong2 wp = *reinterpret_cast<const ulonglong2*>(
                        sWp2D + (og * 5 + q) * 520 + 2 * k);
                    ffma2(acc5[q], a0, wp.x);
                    ffma2(acc5[q], a1, wp.y);
                }
            }
#pragma unroll
            for (int q = 0; q < 5; q++) {
                int o = og * 5 + q;
                float2 v = unpack2(acc5[q]);
                float bb = sBp2[o];
                sPS[(2 * bp) * 40 + o]     = v.x + bb;
                sPS[(2 * bp + 1) * 40 + o] = v.y + bb;
            }
        }
        __syncthreads();

        for (int i = t; i < 640; i += THREADS) {
            int b = i / 20, a = i % 20;
            float mu  = sPS[b * 40 + a];
            float sig = expf(sPS[b * 40 + 20 + a]);
            float inv = sGate[b * 8 + p] / sig;
            sSum1[i] += mu * inv;
            sSum2[i] += inv;
        }
        __syncthreads();
    }

    // ---- final log_prob / entropy ----
    if (t < 32) {
        const int b = t;
        float lp = 0.f, ent = 0.f;
#pragma unroll
        for (int a = 0; a < 20; a++) {
            float s1v = sSum1[b * 20 + a];
            float s2v = sSum2[b * 20 + a];
            float mu = s1v / s2v;
            float z = (sAct[b * 20 + a] - mu) * s2v;
            float ls = -logf(s2v);
            lp  += -0.5f * z * z - ls - LOG_SQRT_2PI;
            ent += 0.5f + LOG_SQRT_2PI + ls;
        }
        size_t row = (size_t)rowBase + b;
        out[row * 2 + 0] = lp;
        out[row * 2 + 1] = ent;
    }
}

extern "C" void kernel_launch(void* const* d_in, const int* in_sizes, int n_in,
                              void* d_out, int out_size)
{
    const float* obs    = (const float*)d_in[0];
    const float* actions= (const float*)d_in[1];
    const float* W1     = (const float*)d_in[2];
    const float* b1     = (const float*)d_in[3];
    const float* W2     = (const float*)d_in[4];
    const float* b2     = (const float*)d_in[5];
    const float* Wp1    = (const float*)d_in[6];
    const float* bp1    = (const float*)d_in[7];
    const float* Wp2    = (const float*)d_in[8];
    const float* bp2    = (const float*)d_in[9];
    const float* Ws1    = (const float*)d_in[10];
    const float* bs1    = (const float*)d_in[11];
    const float* Ws2    = (const float*)d_in[12];
    const float* bs2    = (const float*)d_in[13];
    const float* Ws3    = (const float*)d_in[14];
    const float* bs3    = (const float*)d_in[15];
    const float* Wg1    = (const float*)d_in[16];
    const float* bg1    = (const float*)d_in[17];
    const float* Wg2    = (const float*)d_in[18];
    const float* bg2    = (const float*)d_in[19];
    const float* Wg3    = (const float*)d_in[20];
    const float* bg3    = (const float*)d_in[21];
    const float* Wgate  = (const float*)d_in[22];
    const float* bgate  = (const float*)d_in[23];
    float* out = (float*)d_out;

    cudaFuncSetAttribute(actor_kernel,
                         cudaFuncAttributeMaxDynamicSharedMemorySize, SMEM_BYTES);

    const int grid = 65536 / TILE_B;  // 2048 CTAs
    actor_kernel<<<grid, THREADS, SMEM_BYTES>>>(
        obs, actions, W1, b1, W2, b2, Wp1, bp1, Wp2, bp2,
        Ws1, bs1, Ws2, bs2, Ws3, bs3, Wg1, bg1, Wg2, bg2,
        Wg3, bg3, Wgate, bgate, out);
}

// round 6
// speedup vs baseline: 1.2266x; 1.0008x over previous
#include <cuda_runtime.h>
#include <cstdint>

typedef unsigned long long u64;

#define TILE_B 32
#define THREADS 512
#define APAD 36
#define LOG_SQRT_2PI 0.9189385332046727f

__device__ __forceinline__ u64 bcast2(float x) {
    u64 r;
    asm("mov.b64 %0, {%1,%2};" : "=l"(r) : "f"(x), "f"(x));
    return r;
}
__device__ __forceinline__ void ffma2(u64& d, u64 a, u64 b) {
    asm("fma.rn.f32x2 %0, %1, %2, %0;" : "+l"(d) : "l"(a), "l"(b));
}
__device__ __forceinline__ float2 unpack2(u64 v) {
    float2 f;
    asm("mov.b64 {%0,%1}, %2;" : "=f"(f.x), "=f"(f.y) : "l"(v));
    return f;
}
__device__ __forceinline__ float lrelu(float v) { return v > 0.f ? v : 0.01f * v; }

template<int CPT> struct WVec;
template<> struct WVec<4> { typedef float4 T; };
template<> struct WVec<2> { typedef float2 T; };
template<> struct WVec<1> { typedef float  T; };

__device__ __forceinline__ float getc(const float4& v, int i) {
    return i == 0 ? v.x : i == 1 ? v.y : i == 2 ? v.z : v.w;
}
__device__ __forceinline__ float getc(const float2& v, int i) { return i == 0 ? v.x : v.y; }
__device__ __forceinline__ float getc(const float&  v, int)   { return v; }

// Transposed row-paired GEMM: sAT[k][b] (stride APAD) -> sCT[n][b] (stride APAD).
// Every layer uses COLT=128 (col-groups), RG=4 row-groups, RPT=8 rows/thread.
// Thread computes CPT cols x 8 rows as 4 f32x2 row-pair accumulators per col.
// W prefetched PF k-rows ahead (>= L2 latency).
template <int K, int N, int CPT, int PF, bool RELU>
__device__ __forceinline__ void gemm_T2(
    const float* __restrict__ W, const float* __restrict__ bias,
    const float* __restrict__ sAT, float* __restrict__ sCT)
{
    constexpr int COLT = N / CPT;                     // 128 for all layers
    static_assert(COLT * 4 == THREADS, "mapping");
    typedef typename WVec<CPT>::T WT;

    const int t    = threadIdx.x;
    const int col0 = (t % COLT) * CPT;
    const int row0 = (t / COLT) * 8;                  // RPT = 8

    u64 acc[CPT][4];
#pragma unroll
    for (int c = 0; c < CPT; c++)
#pragma unroll
        for (int j = 0; j < 4; j++) acc[c][j] = 0ull;

    const float* Wc = W + col0;
    WT wbuf[PF];
#pragma unroll
    for (int i = 0; i < PF; i++)
        wbuf[i] = *reinterpret_cast<const WT*>(Wc + (size_t)i * N);

#pragma unroll 1
    for (int kb = 0; kb < K; kb += PF) {
#pragma unroll
        for (int u = 0; u < PF; u++) {
            WT wv = wbuf[u];
            if (kb + PF + u < K)
                wbuf[u] = *reinterpret_cast<const WT*>(Wc + (size_t)(kb + PF + u) * N);
            const ulonglong2* ap = reinterpret_cast<const ulonglong2*>(
                sAT + (kb + u) * APAD + row0);
            const ulonglong2 a01 = ap[0];
            const ulonglong2 a23 = ap[1];
#pragma unroll
            for (int c = 0; c < CPT; c++) {
                const u64 b = bcast2(getc(wv, c));
                ffma2(acc[c][0], a01.x, b);
                ffma2(acc[c][1], a01.y, b);
                ffma2(acc[c][2], a23.x, b);
                ffma2(acc[c][3], a23.y, b);
            }
        }
    }

#pragma unroll
    for (int c = 0; c < CPT; c++) {
        const float bc = bias[col0 + c];
        float* dst = sCT + (size_t)(col0 + c) * APAD + row0;
#pragma unroll
        for (int jj = 0; jj < 2; jj++) {
            float2 v0 = unpack2(acc[c][2 * jj]);
            float2 v1 = unpack2(acc[c][2 * jj + 1]);
            float c0 = v0.x + bc, c1 = v0.y + bc, c2 = v1.x + bc, c3 = v1.y + bc;
            if (RELU) { c0 = lrelu(c0); c1 = lrelu(c1); c2 = lrelu(c2); c3 = lrelu(c3); }
            *reinterpret_cast<float4*>(dst + 4 * jj) = make_float4(c0, c1, c2, c3);
        }
    }
}

// Shared memory layout (floats)
#define OFF_INT    0                    // 256*36 = 9216  (obs_stat^T)
#define OFF_GOALT  9216                 // 128*36 = 4608  (obs_goal^T)
#define OFF_AT     13824                // 512*36 = 18432
#define OFF_BT     32256                // 256*36 = 9216
#define OFF_CT     41472                // 256*36 = 9216  (sg^T / h^T)
#define OFF_WGDUP  50688                // 8*520 = 4160   (Wgate dup'd {w,w})
#define OFF_GATE   54848                // 256
#define OFF_SUM1   55104                // 640
#define OFF_SUM2   55744                // 640
#define OFF_ACT    56384                // 640
#define SMEM_FLOATS 57024
#define SMEM_BYTES (SMEM_FLOATS * 4)    // 228096 B
// p-loop reuse of [INT|GOALT|AT] region (free after W2):
#define OFF_WP2DUP 0                    // 40*520 = 20800 (Wp2[p] dup'd {w,w})
#define OFF_PS     20800                // 32*40 = 1280
#define OFF_BP2    22080                // 40

__global__ __launch_bounds__(THREADS, 1) void actor_kernel(
    const float* __restrict__ obs, const float* __restrict__ actions,
    const float* __restrict__ W1, const float* __restrict__ b1,
    const float* __restrict__ W2, const float* __restrict__ b2,
    const float* __restrict__ Wp1, const float* __restrict__ bp1,
    const float* __restrict__ Wp2, const float* __restrict__ bp2,
    const float* __restrict__ Ws1, const float* __restrict__ bs1,
    const float* __restrict__ Ws2, const float* __restrict__ bs2,
    const float* __restrict__ Ws3, const float* __restrict__ bs3,
    const float* __restrict__ Wg1, const float* __restrict__ bg1,
    const float* __restrict__ Wg2, const float* __restrict__ bg2,
    const float* __restrict__ Wg3, const float* __restrict__ bg3,
    const float* __restrict__ Wgate, const float* __restrict__ bgate,
    float* __restrict__ out)
{
    extern __shared__ float sm[];
    float* sInT  = sm + OFF_INT;
    float* sGoalT= sm + OFF_GOALT;
    float* sAT   = sm + OFF_AT;
    float* sBT   = sm + OFF_BT;
    float* sCT   = sm + OFF_CT;
    float* sWgD  = sm + OFF_WGDUP;
    float* sGate = sm + OFF_GATE;
    float* sSum1 = sm + OFF_SUM1;
    float* sSum2 = sm + OFF_SUM2;
    float* sAct  = sm + OFF_ACT;
    float* sWp2D = sm + OFF_WP2DUP;
    float* sPS   = sm + OFF_PS;
    float* sBp2  = sm + OFF_BP2;

    const int t = threadIdx.x;
    const int rowBase = blockIdx.x * TILE_B;

    // ---- load inputs (transposed), stage dup'd Wgate, init sums ----
    {
        for (int i = t; i < 32 * 96; i += THREADS) {
            int b = i & 31, c4 = i >> 5;
            float4 v = *reinterpret_cast<const float4*>(
                obs + (size_t)(rowBase + b) * 384 + c4 * 4);
            int k = c4 * 4;
            if (k < 256) {
                sInT[(k + 0) * APAD + b] = v.x;
                sInT[(k + 1) * APAD + b] = v.y;
                sInT[(k + 2) * APAD + b] = v.z;
                sInT[(k + 3) * APAD + b] = v.w;
            } else {
                int kg = k - 256;
                sGoalT[(kg + 0) * APAD + b] = v.x;
                sGoalT[(kg + 1) * APAD + b] = v.y;
                sGoalT[(kg + 2) * APAD + b] = v.z;
                sGoalT[(kg + 3) * APAD + b] = v.w;
            }
        }
        for (int i = t; i < 640; i += THREADS) sAct[i] = actions[(size_t)rowBase * 20 + i];
        for (int i = t; i < 2048; i += THREADS) {
            int k = i >> 3, p = i & 7;
            *reinterpret_cast<u64*>(sWgD + p * 520 + 2 * k) = bcast2(Wgate[i]);
        }
        for (int i = t; i < 640; i += THREADS) { sSum1[i] = 0.f; sSum2[i] = 0.f; }
    }
    __syncthreads();

    // ---- gate path (lrelu folded into Ws3/Wg3 epilogue) ----
    gemm_T2<256, 512, 4,  8, true>(Ws1, bs1, sInT,   sAT);  __syncthreads();
    gemm_T2<512, 256, 2, 16, true>(Ws2, bs2, sAT,    sBT);  __syncthreads();
    gemm_T2<256, 128, 1, 16, true>(Ws3, bs3, sBT,    sCT);
    gemm_T2<128, 512, 4,  8, true>(Wg1, bg1, sGoalT, sAT);  __syncthreads();
    gemm_T2<512, 256, 2, 16, true>(Wg2, bg2, sAT,    sBT);  __syncthreads();
    gemm_T2<256, 128, 1, 16, true>(Wg3, bg3, sBT,    sCT + 128 * APAD);
    __syncthreads();

    // ---- gate: w_gate[b][p] = exp(sg[b].Wgate[:,p] + bgate[p]) ----
    if (t < 128) {
        const int bp = t & 15, p = t >> 4;
        const float* wg = sWgD + p * 520;
        u64 acc0 = 0ull, acc1 = 0ull;
        const float* aB = sCT + 2 * bp;
#pragma unroll 4
        for (int k = 0; k < 256; k += 2) {
            ulonglong2 wp = *reinterpret_cast<const ulonglong2*>(wg + 2 * k);
            u64 a0 = *reinterpret_cast<const u64*>(aB + k * APAD);
            u64 a1 = *reinterpret_cast<const u64*>(aB + (k + 1) * APAD);
            ffma2(acc0, a0, wp.x);
            ffma2(acc1, a1, wp.y);
        }
        float2 v0 = unpack2(acc0), v1 = unpack2(acc1);
        float bg = bgate[p];
        sGate[(2 * bp) * 8 + p]     = expf(v0.x + v1.x + bg);
        sGate[(2 * bp + 1) * 8 + p] = expf(v0.y + v1.y + bg);
    }

    // ---- primitive trunk (disjoint smem regions vs gate stage) ----
    gemm_T2<256, 512, 4,  8, true>(W1, b1, sInT, sAT); __syncthreads();
    gemm_T2<512, 256, 2, 16, true>(W2, b2, sAT,  sBT); __syncthreads();
    // [INT|GOALT|AT] now free -> Wp2 dup staging + ps

    for (int p = 0; p < 8; p++) {
        const float* wp2 = Wp2 + p * (256 * 40);
        for (int i = t; i < 256 * 40; i += THREADS) {
            int k = i / 40, o = i % 40;
            *reinterpret_cast<u64*>(sWp2D + o * 520 + 2 * k) = bcast2(wp2[i]);
        }
        if (t < 40) sBp2[t] = bp2[p * 40 + t];
        gemm_T2<256, 256, 2, 16, true>(Wp1 + p * (256 * 256), bp1 + p * 256, sBT, sCT);
        __syncthreads();

        if (t < 128) {
            const int bp = t & 15, og = t >> 4;
            u64 acc5[5];
#pragma unroll
            for (int q = 0; q < 5; q++) acc5[q] = 0ull;
            const float* aB = sCT + 2 * bp;
#pragma unroll 2
            for (int k = 0; k < 256; k += 2) {
                u64 a0 = *reinterpret_cast<const u64*>(aB + k * APAD);
                u64 a1 = *reinterpret_cast<const u64*>(aB + (k + 1) * APAD);
#pragma unroll
                for (int q = 0; q < 5; q++) {
                    ulonglong2 wp = *reinterpret_cast<const ulonglong2*>(
                        sWp2D + (og * 5 + q) * 520 + 2 * k);
                    ffma2(acc5[q], a0, wp.x);
                    ffma2(acc5[q], a1, wp.y);
                }
            }
#pragma unroll
            for (int q = 0; q < 5; q++) {
                int o = og * 5 + q;
                float2 v = unpack2(acc5[q]);
                float bb = sBp2[o];
                sPS[(2 * bp) * 40 + o]     = v.x + bb;
                sPS[(2 * bp + 1) * 40 + o] = v.y + bb;
            }
        }
        __syncthreads();

        for (int i = t; i < 640; i += THREADS) {
            int b = i / 20, a = i % 20;
            float mu  = sPS[b * 40 + a];
            float sig = expf(sPS[b * 40 + 20 + a]);
            float inv = sGate[b * 8 + p] / sig;
            sSum1[i] += mu * inv;
            sSum2[i] += inv;
        }
        __syncthreads();
    }

    // ---- final log_prob / entropy ----
    if (t < 32) {
        const int b = t;
        float lp = 0.f, ent = 0.f;
#pragma unroll
        for (int a = 0; a < 20; a++) {
            float s1v = sSum1[b * 20 + a];
            float s2v = sSum2[b * 20 + a];
            float mu = s1v / s2v;
            float z = (sAct[b * 20 + a] - mu) * s2v;
            float ls = -logf(s2v);
            lp  += -0.5f * z * z - ls - LOG_SQRT_2PI;
            ent += 0.5f + LOG_SQRT_2PI + ls;
        }
        size_t row = (size_t)rowBase + b;
        out[row * 2 + 0] = lp;
        out[row * 2 + 1] = ent;
    }
}

extern "C" void kernel_launch(void* const* d_in, const int* in_sizes, int n_in,
                              void* d_out, int out_size)
{
    const float* obs    = (const float*)d_in[0];
    const float* actions= (const float*)d_in[1];
    const float* W1     = (const float*)d_in[2];
    const float* b1     = (const float*)d_in[3];
    const float* W2     = (const float*)d_in[4];
    const float* b2     = (const float*)d_in[5];
    const float* Wp1    = (const float*)d_in[6];
    const float* bp1    = (const float*)d_in[7];
    const float* Wp2    = (const float*)d_in[8];
    const float* bp2    = (const float*)d_in[9];
    const float* Ws1    = (const float*)d_in[10];
    const float* bs1    = (const float*)d_in[11];
    const float* Ws2    = (const float*)d_in[12];
    const float* bs2    = (const float*)d_in[13];
    const float* Ws3    = (const float*)d_in[14];
    const float* bs3    = (const float*)d_in[15];
    const float* Wg1    = (const float*)d_in[16];
    const float* bg1    = (const float*)d_in[17];
    const float* Wg2    = (const float*)d_in[18];
    const float* bg2    = (const float*)d_in[19];
    const float* Wg3    = (const float*)d_in[20];
    const float* bg3    = (const float*)d_in[21];
    const float* Wgate  = (const float*)d_in[22];
    const float* bgate  = (const float*)d_in[23];
    float* out = (float*)d_out;

    cudaFuncSetAttribute(actor_kernel,
                         cudaFuncAttributeMaxDynamicSharedMemorySize, SMEM_BYTES);

    const int grid = 65536 / TILE_B;  // 2048 CTAs
    actor_kernel<<<grid, THREADS, SMEM_BYTES>>>(
        obs, actions, W1, b1, W2, b2, Wp1, bp1, Wp2, bp2,
        Ws1, bs1, Ws2, bs2, Ws3, bs3, Wg1, bg1, Wg2, bg2,
        Wg3, bg3, Wgate, bgate, out);
}